// round 15
// baseline (speedup 1.0000x reference)
#include <cuda_runtime.h>
#include <math.h>
#include <stdint.h>
#include <string.h>

#define BB 64
#define SS 40
#define TD 39
#define EE 256
#define UU 1024
#define VV 8192
#define G3 3072

// Scratch (device globals; no allocation allowed)
static __device__ float g_gxe[BB * SS * G3];      // encoder x@Wx + b0
static __device__ float g_gxd[BB * TD * G3];      // decoder xt@Wx_bot + b0
static __device__ float g_enc_out[BB * SS * UU];  // encoder hidden sequence
static __device__ float g_P[BB * SS * G3];        // enc_out @ dec_Wx[:U]
static __device__ float g_hdec[BB * TD * UU];     // decoder hidden per step
static __device__ unsigned g_bar[4];              // [cnt, rel, -, -]

// ---------------------------------------------------------------------------
__device__ __forceinline__ float2 fma2(float2 a, float2 b, float2 c) {
    unsigned long long ua, ub, uc;
    memcpy(&ua, &a, 8); memcpy(&ub, &b, 8); memcpy(&uc, &c, 8);
    asm("fma.rn.f32x2 %0, %1, %2, %0;" : "+l"(uc) : "l"(ua), "l"(ub));
    float2 r; memcpy(&r, &uc, 8);
    return r;
}

__device__ __forceinline__ float sigmoidf_(float x) {
    return 1.0f / (1.0f + expf(-x));
}

__device__ __forceinline__ uint32_t f2tf32(float x) {
    uint32_t r;
    asm("cvt.rna.tf32.f32 %0, %1;" : "=r"(r) : "f"(x));
    return r;
}

__device__ __forceinline__ void mma4(float c[4], const uint4& a,
                                     uint32_t b0, uint32_t b1) {
    asm("mma.sync.aligned.m16n8k8.row.col.f32.tf32.tf32.f32 "
        "{%0,%1,%2,%3},{%4,%5,%6,%7},{%8,%9},{%0,%1,%2,%3};"
        : "+f"(c[0]), "+f"(c[1]), "+f"(c[2]), "+f"(c[3])
        : "r"(a.x), "r"(a.y), "r"(a.z), "r"(a.w), "r"(b0), "r"(b1));
}

// bf16 mma m16n8k16 (K=16 per instruction)
__device__ __forceinline__ void mma_bf16(float c[4], const uint4& a,
                                         uint32_t b0, uint32_t b1) {
    asm("mma.sync.aligned.m16n8k16.row.col.f32.bf16.bf16.f32 "
        "{%0,%1,%2,%3},{%4,%5,%6,%7},{%8,%9},{%0,%1,%2,%3};"
        : "+f"(c[0]), "+f"(c[1]), "+f"(c[2]), "+f"(c[3])
        : "r"(a.x), "r"(a.y), "r"(a.z), "r"(a.w), "r"(b0), "r"(b1));
}

// pack {lo16: bf16(lo), hi16: bf16(hi)}  (PTX cvt: first src -> upper half)
__device__ __forceinline__ uint32_t bf16pack2(float lo, float hi) {
    uint32_t r;
    asm("cvt.rn.bf16x2.f32 %0, %1, %2;" : "=r"(r) : "f"(hi), "f"(lo));
    return r;
}
__device__ __forceinline__ float unlo16(uint32_t w) {
    return __uint_as_float(w << 16);
}
__device__ __forceinline__ float unhi16(uint32_t w) {
    return __uint_as_float(w & 0xffff0000u);
}

// ---------------------------------------------------------------------------
// fp32 GEMM (scalar f32x2 path) — step 1 only (feeds the recurrence).
// ---------------------------------------------------------------------------
__global__ __launch_bounds__(256, 2) void gemm_f32(
    const float* __restrict__ A,
    const float* __restrict__ emb, const int* __restrict__ idx,
    int idxTT, int idxStride, int lda,
    const float* __restrict__ W, int ldw,
    const float* __restrict__ bias,
    float* __restrict__ C, int M, int N, int K)
{
    __shared__ __align__(16) float As[2][8][128];
    __shared__ __align__(16) float Ws[2][8][128];

    const int tid = threadIdx.x;
    const int bm = blockIdx.y * 128;
    const int bn = blockIdx.x * 128;

    const int arow_l = tid & 127;
    const int akh    = tid >> 7;
    int mload = bm + arow_l;
    if (mload >= M) mload = M - 1;
    const float* arow;
    if (emb) {
        int r = idx[(mload / idxTT) * idxStride + (mload % idxTT)];
        arow = emb + (size_t)r * lda;
    } else {
        arow = A + (size_t)mload * lda;
    }

    const int wk = tid >> 5;
    const int wn = (tid & 31) * 4;
    const float* wptr = W + (size_t)wk * ldw + bn + wn;

    const int tx = tid & 15, ty = tid >> 4;
    const int r0 = ty * 8, c0 = tx * 8;

    float2 acc[8][4];
#pragma unroll
    for (int r = 0; r < 8; r++)
#pragma unroll
        for (int c = 0; c < 4; c++) acc[r][c] = make_float2(0.f, 0.f);

    const int nIter = K >> 3;

    float4 av = *reinterpret_cast<const float4*>(arow + akh * 4);
    float4 wv = *reinterpret_cast<const float4*>(wptr);
    As[0][akh * 4 + 0][arow_l] = av.x;
    As[0][akh * 4 + 1][arow_l] = av.y;
    As[0][akh * 4 + 2][arow_l] = av.z;
    As[0][akh * 4 + 3][arow_l] = av.w;
    *reinterpret_cast<float4*>(&Ws[0][wk][wn]) = wv;
    __syncthreads();

    for (int it = 0; it < nIter; it++) {
        const int cur = it & 1;
        if (it + 1 < nIter) {
            av = *reinterpret_cast<const float4*>(arow + (it + 1) * 8 + akh * 4);
            wv = *reinterpret_cast<const float4*>(wptr + (size_t)(it + 1) * 8 * ldw);
        }
#pragma unroll
        for (int k = 0; k < 8; k++) {
            float4 a0 = *reinterpret_cast<const float4*>(&As[cur][k][r0]);
            float4 a1 = *reinterpret_cast<const float4*>(&As[cur][k][r0 + 4]);
            float4 w0 = *reinterpret_cast<const float4*>(&Ws[cur][k][c0]);
            float4 w1 = *reinterpret_cast<const float4*>(&Ws[cur][k][c0 + 4]);
            float2 w[4];
            w[0] = make_float2(w0.x, w0.y);
            w[1] = make_float2(w0.z, w0.w);
            w[2] = make_float2(w1.x, w1.y);
            w[3] = make_float2(w1.z, w1.w);
            float ar[8] = {a0.x, a0.y, a0.z, a0.w, a1.x, a1.y, a1.z, a1.w};
#pragma unroll
            for (int r = 0; r < 8; r++) {
                float2 ad = make_float2(ar[r], ar[r]);
#pragma unroll
                for (int c = 0; c < 4; c++)
                    acc[r][c] = fma2(ad, w[c], acc[r][c]);
            }
        }
        if (it + 1 < nIter) {
            const int nxt = cur ^ 1;
            As[nxt][akh * 4 + 0][arow_l] = av.x;
            As[nxt][akh * 4 + 1][arow_l] = av.y;
            As[nxt][akh * 4 + 2][arow_l] = av.z;
            As[nxt][akh * 4 + 3][arow_l] = av.w;
            *reinterpret_cast<float4*>(&Ws[nxt][wk][wn]) = wv;
            __syncthreads();
        }
    }

    float bv[8];
#pragma unroll
    for (int j = 0; j < 8; j++) bv[j] = bias ? bias[bn + c0 + j] : 0.f;
#pragma unroll
    for (int r = 0; r < 8; r++) {
        int mrow = bm + r0 + r;
        if (mrow < M) {
            float4 o0, o1;
            o0.x = acc[r][0].x + bv[0];
            o0.y = acc[r][0].y + bv[1];
            o0.z = acc[r][1].x + bv[2];
            o0.w = acc[r][1].y + bv[3];
            o1.x = acc[r][2].x + bv[4];
            o1.y = acc[r][2].y + bv[5];
            o1.z = acc[r][3].x + bv[6];
            o1.w = acc[r][3].y + bv[7];
            *reinterpret_cast<float4*>(C + (size_t)mrow * N + bn + c0)     = o0;
            *reinterpret_cast<float4*>(C + (size_t)mrow * N + bn + c0 + 4) = o1;
        }
    }
}

// ---------------------------------------------------------------------------
// tf32 tensor-core GEMM v3 (mma.sync m16n8k8) — steps 2, 4, 6.  (R14 WIN)
// 128x128 block, BK=16, 128 threads = 4 warps in 2x2, warp tile 64x64.
// ---------------------------------------------------------------------------
#define TFS 136

__global__ __launch_bounds__(128, 2) void gemm_tf32(
    const float* __restrict__ A,
    const float* __restrict__ emb, const int* __restrict__ idx,
    int idxTT, int idxStride, int lda,
    const float* __restrict__ W, int ldw,
    const float* __restrict__ bias,
    float* __restrict__ C, int M, int N, int K)
{
    __shared__ __align__(16) uint32_t Ast[2][16][TFS];
    __shared__ __align__(16) uint32_t Bst[2][16][TFS];

    const int tid  = threadIdx.x;
    const int lane = tid & 31;
    const int wid  = tid >> 5;
    const int wm   = wid & 1;
    const int wn   = wid >> 1;
    const int g    = lane >> 2;
    const int qt   = lane & 3;

    const int bm = blockIdx.y * 128;
    const int bn = blockIdx.x * 128;

    int mload = bm + tid;
    if (mload >= M) mload = M - 1;
    const float* arow;
    if (emb) {
        int r = idx[(mload / idxTT) * idxStride + (mload % idxTT)];
        arow = emb + (size_t)r * lda;
    } else {
        arow = A + (size_t)mload * lda;
    }

    const int bk = tid >> 3;
    const int bc = (tid & 7) * 4;
    const float* wptr = W + (size_t)bk * ldw + bn + bc;

    float acc[4][8][4];
#pragma unroll
    for (int mf = 0; mf < 4; mf++)
#pragma unroll
        for (int nf = 0; nf < 8; nf++)
#pragma unroll
            for (int q = 0; q < 4; q++) acc[mf][nf][q] = 0.f;

    const int nIter = K >> 4;

    float4 av[4], bvv[4];
#pragma unroll
    for (int j = 0; j < 4; j++) {
        av[j]  = *reinterpret_cast<const float4*>(arow + j * 4);
        bvv[j] = *reinterpret_cast<const float4*>(wptr + j * 32);
    }
    {
        const float* ap = reinterpret_cast<const float*>(av);
#pragma unroll
        for (int j = 0; j < 16; j++) Ast[0][j][tid] = f2tf32(ap[j]);
#pragma unroll
        for (int j = 0; j < 4; j++) {
            uint4 p = make_uint4(f2tf32(bvv[j].x), f2tf32(bvv[j].y),
                                 f2tf32(bvv[j].z), f2tf32(bvv[j].w));
            *reinterpret_cast<uint4*>(&Bst[0][bk][bc + j * 32]) = p;
        }
    }
    __syncthreads();

    for (int it = 0; it < nIter; it++) {
        const int cur = it & 1;
        if (it + 1 < nIter) {
#pragma unroll
            for (int j = 0; j < 4; j++) {
                av[j]  = *reinterpret_cast<const float4*>(arow + (it + 1) * 16 + j * 4);
                bvv[j] = *reinterpret_cast<const float4*>(
                    wptr + (size_t)(it + 1) * 16 * ldw + j * 32);
            }
        }
#pragma unroll
        for (int k8 = 0; k8 < 2; k8++) {
            uint4 afrag[4];
#pragma unroll
            for (int mf = 0; mf < 4; mf++) {
                int R = wm * 64 + mf * 16;
                afrag[mf].x = Ast[cur][k8 * 8 + qt][R + g];
                afrag[mf].y = Ast[cur][k8 * 8 + qt][R + g + 8];
                afrag[mf].z = Ast[cur][k8 * 8 + qt + 4][R + g];
                afrag[mf].w = Ast[cur][k8 * 8 + qt + 4][R + g + 8];
            }
#pragma unroll
            for (int nf = 0; nf < 8; nf++) {
                int cidx = wn * 64 + nf * 8 + g;
                uint32_t b0 = Bst[cur][k8 * 8 + qt][cidx];
                uint32_t b1 = Bst[cur][k8 * 8 + qt + 4][cidx];
#pragma unroll
                for (int mf = 0; mf < 4; mf++)
                    mma4(acc[mf][nf], afrag[mf], b0, b1);
            }
        }
        if (it + 1 < nIter) {
            const int nxt = cur ^ 1;
            const float* ap = reinterpret_cast<const float*>(av);
#pragma unroll
            for (int j = 0; j < 16; j++) Ast[nxt][j][tid] = f2tf32(ap[j]);
#pragma unroll
            for (int j = 0; j < 4; j++) {
                uint4 p = make_uint4(f2tf32(bvv[j].x), f2tf32(bvv[j].y),
                                     f2tf32(bvv[j].z), f2tf32(bvv[j].w));
                *reinterpret_cast<uint4*>(&Bst[nxt][bk][bc + j * 32]) = p;
            }
            __syncthreads();
        }
    }

#pragma unroll
    for (int nf = 0; nf < 8; nf++) {
        int colb = bn + wn * 64 + nf * 8 + qt * 2;
        float b0 = bias ? bias[colb]     : 0.f;
        float b1 = bias ? bias[colb + 1] : 0.f;
#pragma unroll
        for (int mf = 0; mf < 4; mf++) {
            int row0 = bm + wm * 64 + mf * 16 + g;
            if (row0 < M) {
                float2 v = make_float2(acc[mf][nf][0] + b0, acc[mf][nf][1] + b1);
                *reinterpret_cast<float2*>(C + (size_t)row0 * N + colb) = v;
            }
            int row1 = row0 + 8;
            if (row1 < M) {
                float2 v = make_float2(acc[mf][nf][2] + b0, acc[mf][nf][3] + b1);
                *reinterpret_cast<float2*>(C + (size_t)row1 * N + colb) = v;
            }
        }
    }
}

// ---------------------------------------------------------------------------
// Persistent encoder v8: bf16x3 tensor path (m16n8k16), 64 blocks x 512 thr.
// Block owns 16 u-cols (48 gate cols, 6 n8-frags). 16 warps = 8 ksplit pairs;
// pair (2s, 2s+1) shares ksplit s (128 k, 8 chunks of 16k), splits rows 32/32.
// gh = h_hi@W_hi + h_hi@W_lo + h_lo@W_hi (bf16 splits; err ~1e-5/step).
// h staged as packed bf16x2 words [kp][row] stride 72 (bank-clean frag LDS).
// Single staging buffer per ksplit, named pair barriers; W prefetch 1 chunk.
// Benefits vs v6: half the MMA instrs, half the blocks (h traffic, barrier
// arrivals, straggler pool all halve), 4 warps/SMSP.
// ---------------------------------------------------------------------------
#define ENC_BLOCKS 64
#define ENC_THREADS 512
#define KSPL 8
#define BUFW 1152                 /* hi 576 + lo 576 words (8 kp x 72) */
#define GHP_ST 50
#define GHP_WORDS (KSPL * 64 * GHP_ST)
#define ENC_SMEM_BYTES ((KSPL * BUFW + GHP_WORDS) * 4)

#define PAIRBAR(s) asm volatile("bar.sync %0, 64;" :: "r"(1 + (s)) : "memory")

#define E8_LOADH(pf, c)                                                       \
    _Pragma("unroll")                                                         \
    for (int j = 0; j < 4; j++)                                               \
        pf[j] = *reinterpret_cast<const float4*>(hrow + (c) * 16 + j * 4);

#define E8_STAGE(pf)                                                          \
    _Pragma("unroll")                                                         \
    for (int j = 0; j < 4; j++) {                                             \
        uint32_t h0 = bf16pack2(pf[j].x, pf[j].y);                            \
        uint32_t l0 = bf16pack2(pf[j].x - unlo16(h0), pf[j].y - unhi16(h0));  \
        uint32_t h1 = bf16pack2(pf[j].z, pf[j].w);                            \
        uint32_t l1 = bf16pack2(pf[j].z - unlo16(h1), pf[j].w - unhi16(h1));  \
        bufS[(2 * j) * 72 + pt] = h0;                                         \
        bufS[(2 * j + 1) * 72 + pt] = h1;                                     \
        bufS[576 + (2 * j) * 72 + pt] = l0;                                   \
        bufS[576 + (2 * j + 1) * 72 + pt] = l1;                               \
    }

#define E8_LOADW(w, c)                                                        \
    {                                                                         \
        const float* wp_ = wKbase + (size_t)(c) * 16 * G3;                    \
        _Pragma("unroll")                                                     \
        for (int nf = 0; nf < 6; nf++) {                                      \
            const float* q_ = wp_ + (nf >> 1) * UU + (nf & 1) * 8;            \
            w[nf * 4 + 0] = q_[0];                                            \
            w[nf * 4 + 1] = q_[G3];                                           \
            w[nf * 4 + 2] = q_[8 * G3];                                       \
            w[nf * 4 + 3] = q_[9 * G3];                                       \
        }                                                                     \
    }

#define E8_CONSUME(w)                                                         \
    {                                                                         \
        uint4 aH[2], aL[2];                                                   \
        _Pragma("unroll")                                                     \
        for (int mt2 = 0; mt2 < 2; mt2++) {                                   \
            int R = (mh * 2 + mt2) * 16;                                      \
            aH[mt2].x = bufS[qt * 72 + R + g];                                \
            aH[mt2].y = bufS[qt * 72 + R + g + 8];                            \
            aH[mt2].z = bufS[(qt + 4) * 72 + R + g];                          \
            aH[mt2].w = bufS[(qt + 4) * 72 + R + g + 8];                      \
            aL[mt2].x = bufS[576 + qt * 72 + R + g];                          \
            aL[mt2].y = bufS[576 + qt * 72 + R + g + 8];                      \
            aL[mt2].z = bufS[576 + (qt + 4) * 72 + R + g];                    \
            aL[mt2].w = bufS[576 + (qt + 4) * 72 + R + g + 8];                \
        }                                                                     \
        _Pragma("unroll")                                                     \
        for (int nf = 0; nf < 6; nf++) {                                      \
            float w0 = w[nf * 4], w1 = w[nf * 4 + 1];                         \
            float w2 = w[nf * 4 + 2], w3 = w[nf * 4 + 3];                     \
            uint32_t b0h = bf16pack2(w0, w1);                                 \
            uint32_t b1h = bf16pack2(w2, w3);                                 \
            uint32_t b0l = bf16pack2(w0 - unlo16(b0h), w1 - unhi16(b0h));     \
            uint32_t b1l = bf16pack2(w2 - unlo16(b1h), w3 - unhi16(b1h));     \
            mma_bf16(acc[0][nf], aH[0], b0h, b1h);                            \
            mma_bf16(acc[1][nf], aH[1], b0h, b1h);                            \
            mma_bf16(acc[0][nf], aH[0], b0l, b1l);                            \
            mma_bf16(acc[1][nf], aH[1], b0l, b1l);                            \
            mma_bf16(acc[0][nf], aL[0], b0h, b1h);                            \
            mma_bf16(acc[1][nf], aL[1], b0h, b1h);                            \
        }                                                                     \
    }

__global__ __launch_bounds__(ENC_THREADS, 1) void enc_persistent(
    const float* __restrict__ gxe,   // [B*S][3U]  (includes b0)
    const float* __restrict__ Wh,    // [U][3U]
    const float* __restrict__ b1,    // [3U]
    float* __restrict__ enc_out,     // [B*S][U]
    unsigned* bar_cnt, unsigned* bar_rel)
{
    extern __shared__ float sm[];
    uint32_t* stg = reinterpret_cast<uint32_t*>(sm);   // [8 ksplit][1152]
    float* ghp = sm + KSPL * BUFW;                     // [8 ksplit][64][50]

    const int tid  = threadIdx.x;
    const int wid  = tid >> 5;
    const int lane = tid & 31;
    const int s    = wid >> 1;        // ksplit 0..7
    const int mh   = wid & 1;         // row half
    const int g    = lane >> 2;
    const int qt   = lane & 3;
    const int pt   = mh * 32 + lane;  // staging row 0..63
    const int u0   = blockIdx.x * 16;

    uint32_t* bufS = stg + s * BUFW;
    float* ghpS = ghp + s * (64 * GHP_ST);
    const float* wKbase = Wh + (size_t)(s * 128 + 2 * qt) * G3 + u0 + g;

    __shared__ unsigned relbase_s;
    if (tid == 0) relbase_s = *(volatile unsigned*)bar_rel;
    __syncthreads();
    const unsigned relbase = relbase_s;

    // epilogue constants: 2 outputs per thread
    const int du = tid & 15;
    const int bq = tid >> 4;          // 0..31
    const int eu = u0 + du;
    const float b1z = b1[eu], b1r = b1[UU + eu], b1c = b1[2 * UU + eu];

    for (int t = 0; t < SS; t++) {
        if (t > 0) {
            // ---- grid barrier (64 blocks, leader-only fences) ----
            __syncthreads();
            if (tid == 0) {
                __threadfence();
                unsigned old = atomicAdd(bar_cnt, 1u);
                if (old == ENC_BLOCKS - 1) {
                    atomicExch(bar_cnt, 0u);
                    atomicAdd(bar_rel, 1u);
                }
                while (*(volatile unsigned*)bar_rel - relbase < (unsigned)t) {}
                __threadfence();
            }
            __syncthreads();

            float acc[2][6][4];
#pragma unroll
            for (int mt2 = 0; mt2 < 2; mt2++)
#pragma unroll
                for (int nf = 0; nf < 6; nf++)
#pragma unroll
                    for (int q = 0; q < 4; q++) acc[mt2][nf][q] = 0.f;

            const float* hrow = enc_out + (size_t)(t - 1) * UU +
                                (size_t)pt * (SS * UU) + s * 128;

            float4 pf[4];
            float w[24];

            E8_LOADH(pf, 0);
            E8_LOADW(w, 0);
            E8_STAGE(pf);
            E8_LOADH(pf, 1);
            PAIRBAR(s);

            for (int c = 0; c < 8; c++) {
                E8_CONSUME(w);                       // chunk c
                if (c + 1 < 8) E8_LOADW(w, c + 1);   // prefetch W
                PAIRBAR(s);                          // reads of buf done
                if (c + 1 < 8) {
                    E8_STAGE(pf);                    // stage chunk c+1
                    if (c + 2 < 8) E8_LOADH(pf, c + 2);
                    PAIRBAR(s);                      // writes visible
                }
            }

            // write this warp's partial gh
#pragma unroll
            for (int mt2 = 0; mt2 < 2; mt2++)
#pragma unroll
                for (int nf = 0; nf < 6; nf++) {
                    int row = (mh * 2 + mt2) * 16 + g;
                    float* dst = ghpS + row * GHP_ST + nf * 8 + qt * 2;
                    *reinterpret_cast<float2*>(dst) =
                        make_float2(acc[mt2][nf][0], acc[mt2][nf][1]);
                    *reinterpret_cast<float2*>(dst + 8 * GHP_ST) =
                        make_float2(acc[mt2][nf][2], acc[mt2][nf][3]);
                }
        }
        __syncthreads();

        // Epilogue: 2 (b,u) outputs per thread; reduce 8 ksplit partials
#pragma unroll
        for (int i = 0; i < 2; i++) {
            int b = bq + i * 32;
            float ghz = 0.f, ghr = 0.f, ghc = 0.f, hold = 0.f;
            if (t > 0) {
#pragma unroll
                for (int s2 = 0; s2 < KSPL; s2++) {
                    const float* gg = ghp + s2 * (64 * GHP_ST) + b * GHP_ST;
                    ghz += gg[du];
                    ghr += gg[16 + du];
                    ghc += gg[32 + du];
                }
                hold = enc_out[(size_t)(b * SS + t - 1) * UU + eu];
            }
            const float* gxrow = gxe + (size_t)(b * SS + t) * G3;
            float z = sigmoidf_(gxrow[eu] + ghz + b1z);
            float r = sigmoidf_(gxrow[UU + eu] + ghr + b1r);
            float cc = tanhf(gxrow[2 * UU + eu] + r * (ghc + b1c));
            enc_out[(size_t)(b * SS + t) * UU + eu] = z * hold + (1.f - z) * cc;
        }
    }
}

// ---------------------------------------------------------------------------
// Persistent decoder: ONE launch, 64 blocks (one per batch), all 39 steps.
// ---------------------------------------------------------------------------
#define DEC_SMEM_FLOATS (SS * UU + G3 + UU + 64)
#define DEC_SMEM_BYTES (DEC_SMEM_FLOATS * 4)

__global__ __launch_bounds__(256, 1) void dec_persistent(
    const float* __restrict__ enc_out,
    const float* __restrict__ P,
    const float* __restrict__ gxd,
    const float* __restrict__ db1,
    float* __restrict__ hdec)
{
    extern __shared__ float dsm[];
    float* enc_sh = dsm;
    float* gxc    = dsm + SS * UU;
    float* h_sh   = gxc + G3;
    float* wsm    = h_sh + UU;

    const int b   = blockIdx.x;
    const int tid = threadIdx.x;
    const int warp = tid >> 5, lane = tid & 31;

    {
        const float4* src = reinterpret_cast<const float4*>(enc_out + (size_t)b * SS * UU);
        float4* dst = reinterpret_cast<float4*>(enc_sh);
        for (int i = tid; i < SS * UU / 4; i += 256) dst[i] = src[i];
    }
    __syncthreads();
    for (int i = tid; i < UU; i += 256) h_sh[i] = enc_sh[(SS - 1) * UU + i];
    __syncthreads();

    const float* Pb = P + (size_t)b * SS * G3;

    for (int t = 0; t < TD; t++) {
        {
            float acc[5] = {0.f, 0.f, 0.f, 0.f, 0.f};
#pragma unroll 4
            for (int i = 0; i < 32; i++) {
                int uidx = lane + 32 * i;
                float hv = h_sh[uidx];
#pragma unroll
                for (int q = 0; q < 5; q++)
                    acc[q] += hv * enc_sh[(warp * 5 + q) * UU + uidx];
            }
#pragma unroll
            for (int q = 0; q < 5; q++) {
                float v = acc[q];
                for (int o = 16; o; o >>= 1) v += __shfl_xor_sync(0xffffffffu, v, o);
                if (lane == 0) wsm[warp * 5 + q] = v;
            }
        }
        __syncthreads();

        if (tid == 0) {
            float mx = -1e30f;
            for (int s = 0; s < SS; s++) mx = fmaxf(mx, wsm[s]);
            float smv = 0.f;
            for (int s = 0; s < SS; s++) { float e = expf(wsm[s] - mx); wsm[s] = e; smv += e; }
            float inv = 1.f / smv;
            for (int s = 0; s < SS; s++) wsm[s] *= inv;
        }
        __syncthreads();

        {
            float a[12];
#pragma unroll
            for (int i = 0; i < 12; i++) a[i] = 0.f;
            for (int s = 0; s < SS; s++) {
                float w = wsm[s];
                const float* row = Pb + (size_t)s * G3;
#pragma unroll
                for (int i = 0; i < 12; i++)
                    a[i] += w * row[tid + i * 256];
            }
#pragma unroll
            for (int i = 0; i < 12; i++) gxc[tid + i * 256] = a[i];
        }
        __syncthreads();

        {
            const float* gx = gxd + (size_t)(b * TD + t) * G3;
            float* ho = hdec + (size_t)(b * TD + t) * UU;
#pragma unroll
            for (int i = 0; i < 4; i++) {
                int u = tid + i * 256;
                float z = sigmoidf_(gxc[u] + gx[u] + db1[u]);
                float r = sigmoidf_(gxc[UU + u] + gx[UU + u] + db1[UU + u]);
                float c = tanhf(gxc[2 * UU + u] + gx[2 * UU + u] + r * db1[2 * UU + u]);
                float hn = (1.f - z) * c;
                h_sh[u] = hn;
                ho[u] = hn;
            }
        }
        __syncthreads();
    }
}

// ---------------------------------------------------------------------------
extern "C" void kernel_launch(void* const* d_in, const int* in_sizes, int n_in,
                              void* d_out, int out_size)
{
    const int*   inp     = (const int*)d_in[0];
    const int*   targ    = (const int*)d_in[1];
    const float* enc_emb = (const float*)d_in[2];
    const float* enc_Wx  = (const float*)d_in[3];
    const float* enc_Wh  = (const float*)d_in[4];
    const float* enc_b   = (const float*)d_in[5];
    const float* dec_emb = (const float*)d_in[6];
    const float* dec_Wx  = (const float*)d_in[7];
    // d_in[8] = dec_Wh: provably unused (decoder GRU hidden input is zeros)
    const float* dec_b   = (const float*)d_in[9];
    const float* fc_W    = (const float*)d_in[10];
    const float* fc_b    = (const float*)d_in[11];
    float* out = (float*)d_out;

    float *gxe, *gxd, *enc_out, *P, *hdec;
    unsigned* bar;
    cudaGetSymbolAddress((void**)&gxe,     g_gxe);
    cudaGetSymbolAddress((void**)&gxd,     g_gxd);
    cudaGetSymbolAddress((void**)&enc_out, g_enc_out);
    cudaGetSymbolAddress((void**)&P,       g_P);
    cudaGetSymbolAddress((void**)&hdec,    g_hdec);
    cudaGetSymbolAddress((void**)&bar,     g_bar);

    cudaFuncSetAttribute(enc_persistent,
                         cudaFuncAttributeMaxDynamicSharedMemorySize, ENC_SMEM_BYTES);
    cudaFuncSetAttribute(dec_persistent,
                         cudaFuncAttributeMaxDynamicSharedMemorySize, DEC_SMEM_BYTES);

    // 1) Encoder gx (fp32 — feeds the recurrence, keep full precision)
    gemm_f32<<<dim3(G3 / 128, (BB * SS + 127) / 128), 256>>>(
        nullptr, enc_emb, inp, SS, SS, EE,
        enc_Wx, G3, enc_b, gxe, BB * SS, G3, EE);

    // 2) Decoder xt-part gx (tf32 tensor path)
    gemm_tf32<<<dim3(G3 / 128, (BB * TD + 127) / 128), 128>>>(
        nullptr, dec_emb, targ, TD, SS, EE,
        dec_Wx + (size_t)UU * G3, G3, dec_b, gxd, BB * TD, G3, EE);

    // 3) Encoder recurrence: persistent bf16x3 tensor kernel (64 blocks)
    enc_persistent<<<ENC_BLOCKS, ENC_THREADS, ENC_SMEM_BYTES>>>(
        gxe, enc_Wh, enc_b + G3, enc_out, &bar[0], &bar[1]);

    // 4) P = enc_out @ dec_Wx[:U]   (tf32 tensor path)
    gemm_tf32<<<dim3(G3 / 128, (BB * SS + 127) / 128), 128>>>(
        enc_out, nullptr, nullptr, 1, 1, UU,
        dec_Wx, G3, nullptr, P, BB * SS, G3, UU);

    // 5) Decoder recurrence: ONE persistent kernel (batch-parallel)
    dec_persistent<<<BB, 256, DEC_SMEM_BYTES>>>(
        enc_out, P, gxd, dec_b + G3, hdec);

    // 6) Batched output projection (tf32 tensor path)
    gemm_tf32<<<dim3(VV / 128, (BB * TD + 127) / 128), 128>>>(
        hdec, nullptr, nullptr, 1, 1, UU,
        fc_W, VV, fc_b, out, BB * TD, VV, UU);
}

// round 16
// speedup vs baseline: 1.1070x; 1.1070x over previous
#include <cuda_runtime.h>
#include <math.h>
#include <stdint.h>
#include <string.h>

#define BB 64
#define SS 40
#define TD 39
#define EE 256
#define UU 1024
#define VV 8192
#define G3 3072

// Scratch (device globals; no allocation allowed)
static __device__ float g_gxe[BB * SS * G3];      // encoder x@Wx + b0
static __device__ float g_gxd[BB * TD * G3];      // decoder xt@Wx_bot + b0
static __device__ float g_enc_out[BB * SS * UU];  // encoder hidden sequence
static __device__ float g_P[BB * SS * G3];        // enc_out @ dec_Wx[:U]
static __device__ float g_hdec[BB * TD * UU];     // decoder hidden per step
static __device__ unsigned g_bar[4];              // [cnt, rel, -, -]

// ---------------------------------------------------------------------------
__device__ __forceinline__ float2 fma2(float2 a, float2 b, float2 c) {
    unsigned long long ua, ub, uc;
    memcpy(&ua, &a, 8); memcpy(&ub, &b, 8); memcpy(&uc, &c, 8);
    asm("fma.rn.f32x2 %0, %1, %2, %0;" : "+l"(uc) : "l"(ua), "l"(ub));
    float2 r; memcpy(&r, &uc, 8);
    return r;
}

__device__ __forceinline__ float sigmoidf_(float x) {
    return 1.0f / (1.0f + expf(-x));
}

__device__ __forceinline__ uint32_t f2tf32(float x) {
    uint32_t r;
    asm("cvt.rna.tf32.f32 %0, %1;" : "=r"(r) : "f"(x));
    return r;
}

__device__ __forceinline__ void mma4(float c[4], const uint4& a,
                                     uint32_t b0, uint32_t b1) {
    asm("mma.sync.aligned.m16n8k8.row.col.f32.tf32.tf32.f32 "
        "{%0,%1,%2,%3},{%4,%5,%6,%7},{%8,%9},{%0,%1,%2,%3};"
        : "+f"(c[0]), "+f"(c[1]), "+f"(c[2]), "+f"(c[3])
        : "r"(a.x), "r"(a.y), "r"(a.z), "r"(a.w), "r"(b0), "r"(b1));
}

// bf16 mma m16n8k16 (K=16 per instruction)
__device__ __forceinline__ void mma_bf16(float c[4], const uint4& a,
                                         uint32_t b0, uint32_t b1) {
    asm("mma.sync.aligned.m16n8k16.row.col.f32.bf16.bf16.f32 "
        "{%0,%1,%2,%3},{%4,%5,%6,%7},{%8,%9},{%0,%1,%2,%3};"
        : "+f"(c[0]), "+f"(c[1]), "+f"(c[2]), "+f"(c[3])
        : "r"(a.x), "r"(a.y), "r"(a.z), "r"(a.w), "r"(b0), "r"(b1));
}

// pack {lo16: bf16(a), hi16: bf16(b)}
__device__ __forceinline__ uint32_t bf16pack2(float a, float b) {
    uint32_t r;
    asm("cvt.rn.bf16x2.f32 %0, %1, %2;" : "=r"(r) : "f"(b), "f"(a));
    return r;
}
__device__ __forceinline__ float unlo16(uint32_t w) {
    return __uint_as_float(w << 16);
}
__device__ __forceinline__ float unhi16(uint32_t w) {
    return __uint_as_float(w & 0xffff0000u);
}

// ---------------------------------------------------------------------------
// fp32 GEMM (scalar f32x2 path) — step 1 only (feeds the recurrence).
// ---------------------------------------------------------------------------
__global__ __launch_bounds__(256, 2) void gemm_f32(
    const float* __restrict__ A,
    const float* __restrict__ emb, const int* __restrict__ idx,
    int idxTT, int idxStride, int lda,
    const float* __restrict__ W, int ldw,
    const float* __restrict__ bias,
    float* __restrict__ C, int M, int N, int K)
{
    __shared__ __align__(16) float As[2][8][128];
    __shared__ __align__(16) float Ws[2][8][128];

    const int tid = threadIdx.x;
    const int bm = blockIdx.y * 128;
    const int bn = blockIdx.x * 128;

    const int arow_l = tid & 127;
    const int akh    = tid >> 7;
    int mload = bm + arow_l;
    if (mload >= M) mload = M - 1;
    const float* arow;
    if (emb) {
        int r = idx[(mload / idxTT) * idxStride + (mload % idxTT)];
        arow = emb + (size_t)r * lda;
    } else {
        arow = A + (size_t)mload * lda;
    }

    const int wk = tid >> 5;
    const int wn = (tid & 31) * 4;
    const float* wptr = W + (size_t)wk * ldw + bn + wn;

    const int tx = tid & 15, ty = tid >> 4;
    const int r0 = ty * 8, c0 = tx * 8;

    float2 acc[8][4];
#pragma unroll
    for (int r = 0; r < 8; r++)
#pragma unroll
        for (int c = 0; c < 4; c++) acc[r][c] = make_float2(0.f, 0.f);

    const int nIter = K >> 3;

    float4 av = *reinterpret_cast<const float4*>(arow + akh * 4);
    float4 wv = *reinterpret_cast<const float4*>(wptr);
    As[0][akh * 4 + 0][arow_l] = av.x;
    As[0][akh * 4 + 1][arow_l] = av.y;
    As[0][akh * 4 + 2][arow_l] = av.z;
    As[0][akh * 4 + 3][arow_l] = av.w;
    *reinterpret_cast<float4*>(&Ws[0][wk][wn]) = wv;
    __syncthreads();

    for (int it = 0; it < nIter; it++) {
        const int cur = it & 1;
        if (it + 1 < nIter) {
            av = *reinterpret_cast<const float4*>(arow + (it + 1) * 8 + akh * 4);
            wv = *reinterpret_cast<const float4*>(wptr + (size_t)(it + 1) * 8 * ldw);
        }
#pragma unroll
        for (int k = 0; k < 8; k++) {
            float4 a0 = *reinterpret_cast<const float4*>(&As[cur][k][r0]);
            float4 a1 = *reinterpret_cast<const float4*>(&As[cur][k][r0 + 4]);
            float4 w0 = *reinterpret_cast<const float4*>(&Ws[cur][k][c0]);
            float4 w1 = *reinterpret_cast<const float4*>(&Ws[cur][k][c0 + 4]);
            float2 w[4];
            w[0] = make_float2(w0.x, w0.y);
            w[1] = make_float2(w0.z, w0.w);
            w[2] = make_float2(w1.x, w1.y);
            w[3] = make_float2(w1.z, w1.w);
            float ar[8] = {a0.x, a0.y, a0.z, a0.w, a1.x, a1.y, a1.z, a1.w};
#pragma unroll
            for (int r = 0; r < 8; r++) {
                float2 ad = make_float2(ar[r], ar[r]);
#pragma unroll
                for (int c = 0; c < 4; c++)
                    acc[r][c] = fma2(ad, w[c], acc[r][c]);
            }
        }
        if (it + 1 < nIter) {
            const int nxt = cur ^ 1;
            As[nxt][akh * 4 + 0][arow_l] = av.x;
            As[nxt][akh * 4 + 1][arow_l] = av.y;
            As[nxt][akh * 4 + 2][arow_l] = av.z;
            As[nxt][akh * 4 + 3][arow_l] = av.w;
            *reinterpret_cast<float4*>(&Ws[nxt][wk][wn]) = wv;
            __syncthreads();
        }
    }

    float bv[8];
#pragma unroll
    for (int j = 0; j < 8; j++) bv[j] = bias ? bias[bn + c0 + j] : 0.f;
#pragma unroll
    for (int r = 0; r < 8; r++) {
        int mrow = bm + r0 + r;
        if (mrow < M) {
            float4 o0, o1;
            o0.x = acc[r][0].x + bv[0];
            o0.y = acc[r][0].y + bv[1];
            o0.z = acc[r][1].x + bv[2];
            o0.w = acc[r][1].y + bv[3];
            o1.x = acc[r][2].x + bv[4];
            o1.y = acc[r][2].y + bv[5];
            o1.z = acc[r][3].x + bv[6];
            o1.w = acc[r][3].y + bv[7];
            *reinterpret_cast<float4*>(C + (size_t)mrow * N + bn + c0)     = o0;
            *reinterpret_cast<float4*>(C + (size_t)mrow * N + bn + c0 + 4) = o1;
        }
    }
}

// ---------------------------------------------------------------------------
// tf32 tensor-core GEMM v3 (mma.sync m16n8k8) — steps 2, 4, 6.  (R14 WIN)
// 128x128 block, BK=16, 128 threads = 4 warps in 2x2, warp tile 64x64.
// ---------------------------------------------------------------------------
#define TFS 136

__global__ __launch_bounds__(128, 2) void gemm_tf32(
    const float* __restrict__ A,
    const float* __restrict__ emb, const int* __restrict__ idx,
    int idxTT, int idxStride, int lda,
    const float* __restrict__ W, int ldw,
    const float* __restrict__ bias,
    float* __restrict__ C, int M, int N, int K)
{
    __shared__ __align__(16) uint32_t Ast[2][16][TFS];
    __shared__ __align__(16) uint32_t Bst[2][16][TFS];

    const int tid  = threadIdx.x;
    const int lane = tid & 31;
    const int wid  = tid >> 5;
    const int wm   = wid & 1;
    const int wn   = wid >> 1;
    const int g    = lane >> 2;
    const int qt   = lane & 3;

    const int bm = blockIdx.y * 128;
    const int bn = blockIdx.x * 128;

    int mload = bm + tid;
    if (mload >= M) mload = M - 1;
    const float* arow;
    if (emb) {
        int r = idx[(mload / idxTT) * idxStride + (mload % idxTT)];
        arow = emb + (size_t)r * lda;
    } else {
        arow = A + (size_t)mload * lda;
    }

    const int bk = tid >> 3;
    const int bc = (tid & 7) * 4;
    const float* wptr = W + (size_t)bk * ldw + bn + bc;

    float acc[4][8][4];
#pragma unroll
    for (int mf = 0; mf < 4; mf++)
#pragma unroll
        for (int nf = 0; nf < 8; nf++)
#pragma unroll
            for (int q = 0; q < 4; q++) acc[mf][nf][q] = 0.f;

    const int nIter = K >> 4;

    float4 av[4], bvv[4];
#pragma unroll
    for (int j = 0; j < 4; j++) {
        av[j]  = *reinterpret_cast<const float4*>(arow + j * 4);
        bvv[j] = *reinterpret_cast<const float4*>(wptr + j * 32);
    }
    {
        const float* ap = reinterpret_cast<const float*>(av);
#pragma unroll
        for (int j = 0; j < 16; j++) Ast[0][j][tid] = f2tf32(ap[j]);
#pragma unroll
        for (int j = 0; j < 4; j++) {
            uint4 p = make_uint4(f2tf32(bvv[j].x), f2tf32(bvv[j].y),
                                 f2tf32(bvv[j].z), f2tf32(bvv[j].w));
            *reinterpret_cast<uint4*>(&Bst[0][bk][bc + j * 32]) = p;
        }
    }
    __syncthreads();

    for (int it = 0; it < nIter; it++) {
        const int cur = it & 1;
        if (it + 1 < nIter) {
#pragma unroll
            for (int j = 0; j < 4; j++) {
                av[j]  = *reinterpret_cast<const float4*>(arow + (it + 1) * 16 + j * 4);
                bvv[j] = *reinterpret_cast<const float4*>(
                    wptr + (size_t)(it + 1) * 16 * ldw + j * 32);
            }
        }
#pragma unroll
        for (int k8 = 0; k8 < 2; k8++) {
            uint4 afrag[4];
#pragma unroll
            for (int mf = 0; mf < 4; mf++) {
                int R = wm * 64 + mf * 16;
                afrag[mf].x = Ast[cur][k8 * 8 + qt][R + g];
                afrag[mf].y = Ast[cur][k8 * 8 + qt][R + g + 8];
                afrag[mf].z = Ast[cur][k8 * 8 + qt + 4][R + g];
                afrag[mf].w = Ast[cur][k8 * 8 + qt + 4][R + g + 8];
            }
#pragma unroll
            for (int nf = 0; nf < 8; nf++) {
                int cidx = wn * 64 + nf * 8 + g;
                uint32_t b0 = Bst[cur][k8 * 8 + qt][cidx];
                uint32_t b1 = Bst[cur][k8 * 8 + qt + 4][cidx];
#pragma unroll
                for (int mf = 0; mf < 4; mf++)
                    mma4(acc[mf][nf], afrag[mf], b0, b1);
            }
        }
        if (it + 1 < nIter) {
            const int nxt = cur ^ 1;
            const float* ap = reinterpret_cast<const float*>(av);
#pragma unroll
            for (int j = 0; j < 16; j++) Ast[nxt][j][tid] = f2tf32(ap[j]);
#pragma unroll
            for (int j = 0; j < 4; j++) {
                uint4 p = make_uint4(f2tf32(bvv[j].x), f2tf32(bvv[j].y),
                                     f2tf32(bvv[j].z), f2tf32(bvv[j].w));
                *reinterpret_cast<uint4*>(&Bst[nxt][bk][bc + j * 32]) = p;
            }
            __syncthreads();
        }
    }

#pragma unroll
    for (int nf = 0; nf < 8; nf++) {
        int colb = bn + wn * 64 + nf * 8 + qt * 2;
        float b0 = bias ? bias[colb]     : 0.f;
        float b1 = bias ? bias[colb + 1] : 0.f;
#pragma unroll
        for (int mf = 0; mf < 4; mf++) {
            int row0 = bm + wm * 64 + mf * 16 + g;
            if (row0 < M) {
                float2 v = make_float2(acc[mf][nf][0] + b0, acc[mf][nf][1] + b1);
                *reinterpret_cast<float2*>(C + (size_t)row0 * N + colb) = v;
            }
            int row1 = row0 + 8;
            if (row1 < M) {
                float2 v = make_float2(acc[mf][nf][2] + b0, acc[mf][nf][3] + b1);
                *reinterpret_cast<float2*>(C + (size_t)row1 * N + colb) = v;
            }
        }
    }
}

// ---------------------------------------------------------------------------
// Persistent encoder v9: v6 STRUCTURE (128 blocks x 256 thr, 8 warp-ksplits,
// single grid barrier/step) + bf16x3 m16n8k16 fragments (HALF the MMA count
// of tf32-Dekker; maps harness-verified in R15) + W pre-packed bf16 hi/lo in
// smem ONCE (97KB, 40x reuse, conflict-free B LDS via stride 1036).
// gh = h_hi@W_hi + h_hi@W_lo + h_lo@W_hi  (err ~1e-5/step).
// Warp w owns ksplit w: k in [w*128, w*128+128), 8 chunks of 16 k.
// h staged packed [kp][row] stride 72 (STS + A-LDS bank-verified clean),
// single warp-private buffer, __syncwarp ping.
// ---------------------------------------------------------------------------
#define ENC_BLOCKS 128
#define ENC_THREADS 256
#define EWARPS 8
#define WP_ST 1036
#define WP_WORDS (24 * WP_ST)            /* 24864 */
#define STG_BUF 1152                     /* 576 hi + 576 lo (8 kp x 72) */
#define STG_WORDS (EWARPS * STG_BUF)     /* 9216 */
#define GHP_ST 26
#define GHP_WORDS (EWARPS * 64 * GHP_ST) /* 13312 */
#define ENC_SMEM_BYTES ((WP_WORDS + STG_WORDS + GHP_WORDS) * 4)

#define E9_LOAD(c)                                                            \
    _Pragma("unroll")                                                         \
    for (int j = 0; j < 4; j++) {                                             \
        pf[j]     = *reinterpret_cast<const float4*>(r0p + (c) * 16 + j * 4); \
        pf[4 + j] = *reinterpret_cast<const float4*>(r1p + (c) * 16 + j * 4); \
    }

#define E9_STAGE()                                                            \
    _Pragma("unroll")                                                         \
    for (int rr = 0; rr < 2; rr++) {                                          \
        int rowb = lane + rr * 32;                                            \
        _Pragma("unroll")                                                     \
        for (int j = 0; j < 4; j++) {                                         \
            float4 f4 = pf[rr * 4 + j];                                       \
            uint32_t h0 = bf16pack2(f4.x, f4.y);                              \
            uint32_t l0 = bf16pack2(f4.x - unlo16(h0), f4.y - unhi16(h0));    \
            uint32_t h1 = bf16pack2(f4.z, f4.w);                              \
            uint32_t l1 = bf16pack2(f4.z - unlo16(h1), f4.w - unhi16(h1));    \
            bufS[(2 * j) * 72 + rowb] = h0;                                   \
            bufS[576 + (2 * j) * 72 + rowb] = l0;                             \
            bufS[(2 * j + 1) * 72 + rowb] = h1;                               \
            bufS[576 + (2 * j + 1) * 72 + rowb] = l1;                         \
        }                                                                     \
    }

#define E9_CONSUME(c)                                                         \
    {                                                                         \
        uint32_t b0h[3], b1h[3], b0l[3], b1l[3];                              \
        const int kpb = w * 64 + (c) * 8;                                     \
        _Pragma("unroll")                                                     \
        for (int nf = 0; nf < 3; nf++) {                                      \
            int ci = (nf * 8 + g) * WP_ST + kpb;                              \
            b0h[nf] = Wp[ci + qt];                                            \
            b1h[nf] = Wp[ci + qt + 4];                                        \
            b0l[nf] = Wp[ci + 518 + qt];                                      \
            b1l[nf] = Wp[ci + 518 + qt + 4];                                  \
        }                                                                     \
        _Pragma("unroll")                                                     \
        for (int mt = 0; mt < 4; mt++) {                                      \
            int R = mt * 16;                                                  \
            uint4 aH, aL;                                                     \
            aH.x = bufS[qt * 72 + R + g];                                     \
            aH.y = bufS[qt * 72 + R + g + 8];                                 \
            aH.z = bufS[(qt + 4) * 72 + R + g];                               \
            aH.w = bufS[(qt + 4) * 72 + R + g + 8];                           \
            aL.x = bufS[576 + qt * 72 + R + g];                               \
            aL.y = bufS[576 + qt * 72 + R + g + 8];                           \
            aL.z = bufS[576 + (qt + 4) * 72 + R + g];                         \
            aL.w = bufS[576 + (qt + 4) * 72 + R + g + 8];                     \
            _Pragma("unroll")                                                 \
            for (int nf = 0; nf < 3; nf++) {                                  \
                mma_bf16(acc[mt][nf], aH, b0h[nf], b1h[nf]);                  \
                mma_bf16(acc[mt][nf], aH, b0l[nf], b1l[nf]);                  \
                mma_bf16(acc[mt][nf], aL, b0h[nf], b1h[nf]);                  \
            }                                                                 \
        }                                                                     \
    }

__global__ __launch_bounds__(ENC_THREADS, 1) void enc_persistent(
    const float* __restrict__ gxe,   // [B*S][3U]  (includes b0)
    const float* __restrict__ Wh,    // [U][3U]
    const float* __restrict__ b1,    // [3U]
    float* __restrict__ enc_out,     // [B*S][U]
    unsigned* bar_cnt, unsigned* bar_rel)
{
    extern __shared__ float sm[];
    uint32_t* Wp  = reinterpret_cast<uint32_t*>(sm);          // [24][1036]
    uint32_t* stg = reinterpret_cast<uint32_t*>(sm) + WP_WORDS;
    float* ghp = sm + WP_WORDS + STG_WORDS;                   // [8][64][26]

    const int tid  = threadIdx.x;
    const int w    = tid >> 5;
    const int lane = tid & 31;
    const int g    = lane >> 2;
    const int qt   = lane & 3;
    const int bi   = blockIdx.x;
    const int u0   = bi * 8;

    uint32_t* bufS = stg + w * STG_BUF;
    float* ghpW = ghp + w * 64 * GHP_ST;

    // Pack W slice (24 cols x 1024 k) to bf16 hi/lo in smem, ONCE.
    for (int i = tid; i < 24 * 512; i += ENC_THREADS) {
        int col = i >> 9;            // 0..23
        int kp  = i & 511;
        int gate = col >> 3, gg = col & 7;
        float w0 = Wh[(size_t)(2 * kp) * G3 + gate * UU + u0 + gg];
        float w1 = Wh[(size_t)(2 * kp + 1) * G3 + gate * UU + u0 + gg];
        uint32_t hi = bf16pack2(w0, w1);
        uint32_t lo = bf16pack2(w0 - unlo16(hi), w1 - unhi16(hi));
        Wp[col * WP_ST + kp] = hi;
        Wp[col * WP_ST + 518 + kp] = lo;
    }

    __shared__ unsigned relbase_s;
    if (tid == 0) relbase_s = *(volatile unsigned*)bar_rel;
    __syncthreads();
    const unsigned relbase = relbase_s;

    const int edu = tid & 7;
    const int eu  = u0 + edu;
    const float b1z = b1[eu], b1r = b1[UU + eu], b1c = b1[2 * UU + eu];

    for (int t = 0; t < SS; t++) {
        if (t > 0) {
            // ---- grid barrier (leader-only fences) ----
            __syncthreads();
            if (tid == 0) {
                __threadfence();
                unsigned old = atomicAdd(bar_cnt, 1u);
                if (old == ENC_BLOCKS - 1) {
                    atomicExch(bar_cnt, 0u);
                    atomicAdd(bar_rel, 1u);
                }
                while (*(volatile unsigned*)bar_rel - relbase < (unsigned)t) {}
                __threadfence();
            }
            __syncthreads();

            float acc[4][3][4];
#pragma unroll
            for (int mt = 0; mt < 4; mt++)
#pragma unroll
                for (int nf = 0; nf < 3; nf++)
#pragma unroll
                    for (int q = 0; q < 4; q++) acc[mt][nf][q] = 0.f;

            const float* hb = enc_out + (size_t)(t - 1) * UU + w * 128;
            const float* r0p = hb + (size_t)lane * (SS * UU);
            const float* r1p = hb + (size_t)(lane + 32) * (SS * UU);

            float4 pf[8];
            E9_LOAD(0);
            for (int c = 0; c < 8; c++) {
                E9_STAGE();
                __syncwarp();
                if (c + 1 < 8) E9_LOAD(c + 1);
                E9_CONSUME(c);
                __syncwarp();
            }

            // write this warp's partial gh
#pragma unroll
            for (int mt = 0; mt < 4; mt++)
#pragma unroll
                for (int nf = 0; nf < 3; nf++) {
                    int r0 = mt * 16 + g;
                    float* dst = ghpW + r0 * GHP_ST + nf * 8 + qt * 2;
                    *reinterpret_cast<float2*>(dst) =
                        make_float2(acc[mt][nf][0], acc[mt][nf][1]);
                    *reinterpret_cast<float2*>(dst + 8 * GHP_ST) =
                        make_float2(acc[mt][nf][2], acc[mt][nf][3]);
                }
        }
        __syncthreads();

        // Epilogue: 2 (b,u) outputs per thread; reduce 8 ksplit partials
#pragma unroll
        for (int i = 0; i < 2; i++) {
            int b = (tid >> 3) + i * 32;
            float ghz = 0.f, ghr = 0.f, ghc = 0.f, hold = 0.f;
            if (t > 0) {
#pragma unroll
                for (int w2 = 0; w2 < EWARPS; w2++) {
                    const float* gg2 = ghp + w2 * (64 * GHP_ST) + b * GHP_ST;
                    ghz += gg2[edu];
                    ghr += gg2[8 + edu];
                    ghc += gg2[16 + edu];
                }
                hold = enc_out[(size_t)(b * SS + t - 1) * UU + eu];
            }
            const float* gxrow = gxe + (size_t)(b * SS + t) * G3;
            float z = sigmoidf_(gxrow[eu] + ghz + b1z);
            float r = sigmoidf_(gxrow[UU + eu] + ghr + b1r);
            float cc = tanhf(gxrow[2 * UU + eu] + r * (ghc + b1c));
            enc_out[(size_t)(b * SS + t) * UU + eu] = z * hold + (1.f - z) * cc;
        }
    }
}

// ---------------------------------------------------------------------------
// Persistent decoder: ONE launch, 64 blocks (one per batch), all 39 steps.
// ---------------------------------------------------------------------------
#define DEC_SMEM_FLOATS (SS * UU + G3 + UU + 64)
#define DEC_SMEM_BYTES (DEC_SMEM_FLOATS * 4)

__global__ __launch_bounds__(256, 1) void dec_persistent(
    const float* __restrict__ enc_out,
    const float* __restrict__ P,
    const float* __restrict__ gxd,
    const float* __restrict__ db1,
    float* __restrict__ hdec)
{
    extern __shared__ float dsm[];
    float* enc_sh = dsm;
    float* gxc    = dsm + SS * UU;
    float* h_sh   = gxc + G3;
    float* wsm    = h_sh + UU;

    const int b   = blockIdx.x;
    const int tid = threadIdx.x;
    const int warp = tid >> 5, lane = tid & 31;

    {
        const float4* src = reinterpret_cast<const float4*>(enc_out + (size_t)b * SS * UU);
        float4* dst = reinterpret_cast<float4*>(enc_sh);
        for (int i = tid; i < SS * UU / 4; i += 256) dst[i] = src[i];
    }
    __syncthreads();
    for (int i = tid; i < UU; i += 256) h_sh[i] = enc_sh[(SS - 1) * UU + i];
    __syncthreads();

    const float* Pb = P + (size_t)b * SS * G3;

    for (int t = 0; t < TD; t++) {
        {
            float acc[5] = {0.f, 0.f, 0.f, 0.f, 0.f};
#pragma unroll 4
            for (int i = 0; i < 32; i++) {
                int uidx = lane + 32 * i;
                float hv = h_sh[uidx];
#pragma unroll
                for (int q = 0; q < 5; q++)
                    acc[q] += hv * enc_sh[(warp * 5 + q) * UU + uidx];
            }
#pragma unroll
            for (int q = 0; q < 5; q++) {
                float v = acc[q];
                for (int o = 16; o; o >>= 1) v += __shfl_xor_sync(0xffffffffu, v, o);
                if (lane == 0) wsm[warp * 5 + q] = v;
            }
        }
        __syncthreads();

        if (tid == 0) {
            float mx = -1e30f;
            for (int s = 0; s < SS; s++) mx = fmaxf(mx, wsm[s]);
            float smv = 0.f;
            for (int s = 0; s < SS; s++) { float e = expf(wsm[s] - mx); wsm[s] = e; smv += e; }
            float inv = 1.f / smv;
            for (int s = 0; s < SS; s++) wsm[s] *= inv;
        }
        __syncthreads();

        {
            float a[12];
#pragma unroll
            for (int i = 0; i < 12; i++) a[i] = 0.f;
            for (int s = 0; s < SS; s++) {
                float w = wsm[s];
                const float* row = Pb + (size_t)s * G3;
#pragma unroll
                for (int i = 0; i < 12; i++)
                    a[i] += w * row[tid + i * 256];
            }
#pragma unroll
            for (int i = 0; i < 12; i++) gxc[tid + i * 256] = a[i];
        }
        __syncthreads();

        {
            const float* gx = gxd + (size_t)(b * TD + t) * G3;
            float* ho = hdec + (size_t)(b * TD + t) * UU;
#pragma unroll
            for (int i = 0; i < 4; i++) {
                int u = tid + i * 256;
                float z = sigmoidf_(gxc[u] + gx[u] + db1[u]);
                float r = sigmoidf_(gxc[UU + u] + gx[UU + u] + db1[UU + u]);
                float c = tanhf(gxc[2 * UU + u] + gx[2 * UU + u] + r * db1[2 * UU + u]);
                float hn = (1.f - z) * c;
                h_sh[u] = hn;
                ho[u] = hn;
            }
        }
        __syncthreads();
    }
}

// ---------------------------------------------------------------------------
extern "C" void kernel_launch(void* const* d_in, const int* in_sizes, int n_in,
                              void* d_out, int out_size)
{
    const int*   inp     = (const int*)d_in[0];
    const int*   targ    = (const int*)d_in[1];
    const float* enc_emb = (const float*)d_in[2];
    const float* enc_Wx  = (const float*)d_in[3];
    const float* enc_Wh  = (const float*)d_in[4];
    const float* enc_b   = (const float*)d_in[5];
    const float* dec_emb = (const float*)d_in[6];
    const float* dec_Wx  = (const float*)d_in[7];
    // d_in[8] = dec_Wh: provably unused (decoder GRU hidden input is zeros)
    const float* dec_b   = (const float*)d_in[9];
    const float* fc_W    = (const float*)d_in[10];
    const float* fc_b    = (const float*)d_in[11];
    float* out = (float*)d_out;

    float *gxe, *gxd, *enc_out, *P, *hdec;
    unsigned* bar;
    cudaGetSymbolAddress((void**)&gxe,     g_gxe);
    cudaGetSymbolAddress((void**)&gxd,     g_gxd);
    cudaGetSymbolAddress((void**)&enc_out, g_enc_out);
    cudaGetSymbolAddress((void**)&P,       g_P);
    cudaGetSymbolAddress((void**)&hdec,    g_hdec);
    cudaGetSymbolAddress((void**)&bar,     g_bar);

    cudaFuncSetAttribute(enc_persistent,
                         cudaFuncAttributeMaxDynamicSharedMemorySize, ENC_SMEM_BYTES);
    cudaFuncSetAttribute(dec_persistent,
                         cudaFuncAttributeMaxDynamicSharedMemorySize, DEC_SMEM_BYTES);

    // 1) Encoder gx (fp32 — feeds the recurrence, keep full precision)
    gemm_f32<<<dim3(G3 / 128, (BB * SS + 127) / 128), 256>>>(
        nullptr, enc_emb, inp, SS, SS, EE,
        enc_Wx, G3, enc_b, gxe, BB * SS, G3, EE);

    // 2) Decoder xt-part gx (tf32 tensor path)
    gemm_tf32<<<dim3(G3 / 128, (BB * TD + 127) / 128), 128>>>(
        nullptr, dec_emb, targ, TD, SS, EE,
        dec_Wx + (size_t)UU * G3, G3, dec_b, gxd, BB * TD, G3, EE);

    // 3) Encoder recurrence: persistent bf16x3 tensor kernel (v6 structure)
    enc_persistent<<<ENC_BLOCKS, ENC_THREADS, ENC_SMEM_BYTES>>>(
        gxe, enc_Wh, enc_b + G3, enc_out, &bar[0], &bar[1]);

    // 4) P = enc_out @ dec_Wx[:U]   (tf32 tensor path)
    gemm_tf32<<<dim3(G3 / 128, (BB * SS + 127) / 128), 128>>>(
        enc_out, nullptr, nullptr, 1, 1, UU,
        dec_Wx, G3, nullptr, P, BB * SS, G3, UU);

    // 5) Decoder recurrence: ONE persistent kernel (batch-parallel)
    dec_persistent<<<BB, 256, DEC_SMEM_BYTES>>>(
        enc_out, P, gxd, dec_b + G3, hdec);

    // 6) Batched output projection (tf32 tensor path)
    gemm_tf32<<<dim3(VV / 128, (BB * TD + 127) / 128), 128>>>(
        hdec, nullptr, nullptr, 1, 1, UU,
        fc_W, VV, fc_b, out, BB * TD, VV, UU);
}

// round 17
// speedup vs baseline: 1.1468x; 1.0359x over previous
#include <cuda_runtime.h>
#include <math.h>
#include <stdint.h>
#include <string.h>

#define BB 64
#define SS 40
#define TD 39
#define EE 256
#define UU 1024
#define VV 8192
#define G3 3072

// Scratch (device globals; no allocation allowed)
static __device__ float g_gxe[BB * SS * G3];      // encoder x@Wx + b0
static __device__ float g_gxd[BB * TD * G3];      // decoder xt@Wx_bot + b0
static __device__ float g_enc_out[BB * SS * UU];  // encoder hidden sequence
static __device__ float g_P[BB * SS * G3];        // enc_out @ dec_Wx[:U]
static __device__ float g_hdec[BB * TD * UU];     // decoder hidden per step
static __device__ unsigned g_bar[4];              // [cnt, rel, -, -]

// ---------------------------------------------------------------------------
__device__ __forceinline__ float sigmoidf_(float x) {
    return 1.0f / (1.0f + expf(-x));
}

__device__ __forceinline__ uint32_t f2tf32(float x) {
    uint32_t r;
    asm("cvt.rna.tf32.f32 %0, %1;" : "=r"(r) : "f"(x));
    return r;
}

__device__ __forceinline__ void mma4(float c[4], const uint4& a,
                                     uint32_t b0, uint32_t b1) {
    asm("mma.sync.aligned.m16n8k8.row.col.f32.tf32.tf32.f32 "
        "{%0,%1,%2,%3},{%4,%5,%6,%7},{%8,%9},{%0,%1,%2,%3};"
        : "+f"(c[0]), "+f"(c[1]), "+f"(c[2]), "+f"(c[3])
        : "r"(a.x), "r"(a.y), "r"(a.z), "r"(a.w), "r"(b0), "r"(b1));
}

// bf16 mma m16n8k16 (K=16 per instruction)
__device__ __forceinline__ void mma_bf16(float c[4], const uint4& a,
                                         uint32_t b0, uint32_t b1) {
    asm("mma.sync.aligned.m16n8k16.row.col.f32.bf16.bf16.f32 "
        "{%0,%1,%2,%3},{%4,%5,%6,%7},{%8,%9},{%0,%1,%2,%3};"
        : "+f"(c[0]), "+f"(c[1]), "+f"(c[2]), "+f"(c[3])
        : "r"(a.x), "r"(a.y), "r"(a.z), "r"(a.w), "r"(b0), "r"(b1));
}

// pack {lo16: bf16(a), hi16: bf16(b)}
__device__ __forceinline__ uint32_t bf16pack2(float a, float b) {
    uint32_t r;
    asm("cvt.rn.bf16x2.f32 %0, %1, %2;" : "=r"(r) : "f"(b), "f"(a));
    return r;
}
__device__ __forceinline__ float unlo16(uint32_t w) {
    return __uint_as_float(w << 16);
}
__device__ __forceinline__ float unhi16(uint32_t w) {
    return __uint_as_float(w & 0xffff0000u);
}

// ---------------------------------------------------------------------------
// tf32 tensor-core GEMM v3 (mma.sync m16n8k8) — steps 1, 2, 4, 6.
// 128x128 block, BK=16, 128 threads = 4 warps in 2x2, warp tile 64x64.
// ---------------------------------------------------------------------------
#define TFS 136

__global__ __launch_bounds__(128, 2) void gemm_tf32(
    const float* __restrict__ A,
    const float* __restrict__ emb, const int* __restrict__ idx,
    int idxTT, int idxStride, int lda,
    const float* __restrict__ W, int ldw,
    const float* __restrict__ bias,
    float* __restrict__ C, int M, int N, int K)
{
    __shared__ __align__(16) uint32_t Ast[2][16][TFS];
    __shared__ __align__(16) uint32_t Bst[2][16][TFS];

    const int tid  = threadIdx.x;
    const int lane = tid & 31;
    const int wid  = tid >> 5;
    const int wm   = wid & 1;
    const int wn   = wid >> 1;
    const int g    = lane >> 2;
    const int qt   = lane & 3;

    const int bm = blockIdx.y * 128;
    const int bn = blockIdx.x * 128;

    int mload = bm + tid;
    if (mload >= M) mload = M - 1;
    const float* arow;
    if (emb) {
        int r = idx[(mload / idxTT) * idxStride + (mload % idxTT)];
        arow = emb + (size_t)r * lda;
    } else {
        arow = A + (size_t)mload * lda;
    }

    const int bk = tid >> 3;
    const int bc = (tid & 7) * 4;
    const float* wptr = W + (size_t)bk * ldw + bn + bc;

    float acc[4][8][4];
#pragma unroll
    for (int mf = 0; mf < 4; mf++)
#pragma unroll
        for (int nf = 0; nf < 8; nf++)
#pragma unroll
            for (int q = 0; q < 4; q++) acc[mf][nf][q] = 0.f;

    const int nIter = K >> 4;

    float4 av[4], bvv[4];
#pragma unroll
    for (int j = 0; j < 4; j++) {
        av[j]  = *reinterpret_cast<const float4*>(arow + j * 4);
        bvv[j] = *reinterpret_cast<const float4*>(wptr + j * 32);
    }
    {
        const float* ap = reinterpret_cast<const float*>(av);
#pragma unroll
        for (int j = 0; j < 16; j++) Ast[0][j][tid] = f2tf32(ap[j]);
#pragma unroll
        for (int j = 0; j < 4; j++) {
            uint4 p = make_uint4(f2tf32(bvv[j].x), f2tf32(bvv[j].y),
                                 f2tf32(bvv[j].z), f2tf32(bvv[j].w));
            *reinterpret_cast<uint4*>(&Bst[0][bk][bc + j * 32]) = p;
        }
    }
    __syncthreads();

    for (int it = 0; it < nIter; it++) {
        const int cur = it & 1;
        if (it + 1 < nIter) {
#pragma unroll
            for (int j = 0; j < 4; j++) {
                av[j]  = *reinterpret_cast<const float4*>(arow + (it + 1) * 16 + j * 4);
                bvv[j] = *reinterpret_cast<const float4*>(
                    wptr + (size_t)(it + 1) * 16 * ldw + j * 32);
            }
        }
#pragma unroll
        for (int k8 = 0; k8 < 2; k8++) {
            uint4 afrag[4];
#pragma unroll
            for (int mf = 0; mf < 4; mf++) {
                int R = wm * 64 + mf * 16;
                afrag[mf].x = Ast[cur][k8 * 8 + qt][R + g];
                afrag[mf].y = Ast[cur][k8 * 8 + qt][R + g + 8];
                afrag[mf].z = Ast[cur][k8 * 8 + qt + 4][R + g];
                afrag[mf].w = Ast[cur][k8 * 8 + qt + 4][R + g + 8];
            }
#pragma unroll
            for (int nf = 0; nf < 8; nf++) {
                int cidx = wn * 64 + nf * 8 + g;
                uint32_t b0 = Bst[cur][k8 * 8 + qt][cidx];
                uint32_t b1 = Bst[cur][k8 * 8 + qt + 4][cidx];
#pragma unroll
                for (int mf = 0; mf < 4; mf++)
                    mma4(acc[mf][nf], afrag[mf], b0, b1);
            }
        }
        if (it + 1 < nIter) {
            const int nxt = cur ^ 1;
            const float* ap = reinterpret_cast<const float*>(av);
#pragma unroll
            for (int j = 0; j < 16; j++) Ast[nxt][j][tid] = f2tf32(ap[j]);
#pragma unroll
            for (int j = 0; j < 4; j++) {
                uint4 p = make_uint4(f2tf32(bvv[j].x), f2tf32(bvv[j].y),
                                     f2tf32(bvv[j].z), f2tf32(bvv[j].w));
                *reinterpret_cast<uint4*>(&Bst[nxt][bk][bc + j * 32]) = p;
            }
            __syncthreads();
        }
    }

#pragma unroll
    for (int nf = 0; nf < 8; nf++) {
        int colb = bn + wn * 64 + nf * 8 + qt * 2;
        float b0 = bias ? bias[colb]     : 0.f;
        float b1 = bias ? bias[colb + 1] : 0.f;
#pragma unroll
        for (int mf = 0; mf < 4; mf++) {
            int row0 = bm + wm * 64 + mf * 16 + g;
            if (row0 < M) {
                float2 v = make_float2(acc[mf][nf][0] + b0, acc[mf][nf][1] + b1);
                *reinterpret_cast<float2*>(C + (size_t)row0 * N + colb) = v;
            }
            int row1 = row0 + 8;
            if (row1 < M) {
                float2 v = make_float2(acc[mf][nf][2] + b0, acc[mf][nf][3] + b1);
                *reinterpret_cast<float2*>(C + (size_t)row1 * N + colb) = v;
            }
        }
    }
}

// ---------------------------------------------------------------------------
// Persistent encoder v9 (R16 WIN): 128 blocks x 256 thr, 8 warp-ksplits,
// single grid barrier/step, bf16x3 m16n8k16, W pre-packed bf16 hi/lo in smem.
// ---------------------------------------------------------------------------
#define ENC_BLOCKS 128
#define ENC_THREADS 256
#define EWARPS 8
#define WP_ST 1036
#define WP_WORDS (24 * WP_ST)
#define STG_BUF 1152
#define STG_WORDS (EWARPS * STG_BUF)
#define GHP_ST 26
#define GHP_WORDS (EWARPS * 64 * GHP_ST)
#define ENC_SMEM_BYTES ((WP_WORDS + STG_WORDS + GHP_WORDS) * 4)

#define E9_LOAD(c)                                                            \
    _Pragma("unroll")                                                         \
    for (int j = 0; j < 4; j++) {                                             \
        pf[j]     = *reinterpret_cast<const float4*>(r0p + (c) * 16 + j * 4); \
        pf[4 + j] = *reinterpret_cast<const float4*>(r1p + (c) * 16 + j * 4); \
    }

#define E9_STAGE()                                                            \
    _Pragma("unroll")                                                         \
    for (int rr = 0; rr < 2; rr++) {                                          \
        int rowb = lane + rr * 32;                                            \
        _Pragma("unroll")                                                     \
        for (int j = 0; j < 4; j++) {                                         \
            float4 f4 = pf[rr * 4 + j];                                       \
            uint32_t h0 = bf16pack2(f4.x, f4.y);                              \
            uint32_t l0 = bf16pack2(f4.x - unlo16(h0), f4.y - unhi16(h0));    \
            uint32_t h1 = bf16pack2(f4.z, f4.w);                              \
            uint32_t l1 = bf16pack2(f4.z - unlo16(h1), f4.w - unhi16(h1));    \
            bufS[(2 * j) * 72 + rowb] = h0;                                   \
            bufS[576 + (2 * j) * 72 + rowb] = l0;                             \
            bufS[(2 * j + 1) * 72 + rowb] = h1;                               \
            bufS[576 + (2 * j + 1) * 72 + rowb] = l1;                         \
        }                                                                     \
    }

#define E9_CONSUME(c)                                                         \
    {                                                                         \
        uint32_t b0h[3], b1h[3], b0l[3], b1l[3];                              \
        const int kpb = w * 64 + (c) * 8;                                     \
        _Pragma("unroll")                                                     \
        for (int nf = 0; nf < 3; nf++) {                                      \
            int ci = (nf * 8 + g) * WP_ST + kpb;                              \
            b0h[nf] = Wp[ci + qt];                                            \
            b1h[nf] = Wp[ci + qt + 4];                                        \
            b0l[nf] = Wp[ci + 518 + qt];                                      \
            b1l[nf] = Wp[ci + 518 + qt + 4];                                  \
        }                                                                     \
        _Pragma("unroll")                                                     \
        for (int mt = 0; mt < 4; mt++) {                                      \
            int R = mt * 16;                                                  \
            uint4 aH, aL;                                                     \
            aH.x = bufS[qt * 72 + R + g];                                     \
            aH.y = bufS[qt * 72 + R + g + 8];                                 \
            aH.z = bufS[(qt + 4) * 72 + R + g];                               \
            aH.w = bufS[(qt + 4) * 72 + R + g + 8];                           \
            aL.x = bufS[576 + qt * 72 + R + g];                               \
            aL.y = bufS[576 + qt * 72 + R + g + 8];                           \
            aL.z = bufS[576 + (qt + 4) * 72 + R + g];                         \
            aL.w = bufS[576 + (qt + 4) * 72 + R + g + 8];                     \
            _Pragma("unroll")                                                 \
            for (int nf = 0; nf < 3; nf++) {                                  \
                mma_bf16(acc[mt][nf], aH, b0h[nf], b1h[nf]);                  \
                mma_bf16(acc[mt][nf], aH, b0l[nf], b1l[nf]);                  \
                mma_bf16(acc[mt][nf], aL, b0h[nf], b1h[nf]);                  \
            }                                                                 \
        }                                                                     \
    }

__global__ __launch_bounds__(ENC_THREADS, 1) void enc_persistent(
    const float* __restrict__ gxe,   // [B*S][3U]  (includes b0)
    const float* __restrict__ Wh,    // [U][3U]
    const float* __restrict__ b1,    // [3U]
    float* __restrict__ enc_out,     // [B*S][U]
    unsigned* bar_cnt, unsigned* bar_rel)
{
    extern __shared__ float sm[];
    uint32_t* Wp  = reinterpret_cast<uint32_t*>(sm);          // [24][1036]
    uint32_t* stg = reinterpret_cast<uint32_t*>(sm) + WP_WORDS;
    float* ghp = sm + WP_WORDS + STG_WORDS;                   // [8][64][26]

    const int tid  = threadIdx.x;
    const int w    = tid >> 5;
    const int lane = tid & 31;
    const int g    = lane >> 2;
    const int qt   = lane & 3;
    const int bi   = blockIdx.x;
    const int u0   = bi * 8;

    uint32_t* bufS = stg + w * STG_BUF;
    float* ghpW = ghp + w * 64 * GHP_ST;

    // Pack W slice (24 cols x 1024 k) to bf16 hi/lo in smem, ONCE.
    for (int i = tid; i < 24 * 512; i += ENC_THREADS) {
        int col = i >> 9;            // 0..23
        int kp  = i & 511;
        int gate = col >> 3, gg = col & 7;
        float w0 = Wh[(size_t)(2 * kp) * G3 + gate * UU + u0 + gg];
        float w1 = Wh[(size_t)(2 * kp + 1) * G3 + gate * UU + u0 + gg];
        uint32_t hi = bf16pack2(w0, w1);
        uint32_t lo = bf16pack2(w0 - unlo16(hi), w1 - unhi16(hi));
        Wp[col * WP_ST + kp] = hi;
        Wp[col * WP_ST + 518 + kp] = lo;
    }

    __shared__ unsigned relbase_s;
    if (tid == 0) relbase_s = *(volatile unsigned*)bar_rel;
    __syncthreads();
    const unsigned relbase = relbase_s;

    const int edu = tid & 7;
    const int eu  = u0 + edu;
    const float b1z = b1[eu], b1r = b1[UU + eu], b1c = b1[2 * UU + eu];

    for (int t = 0; t < SS; t++) {
        if (t > 0) {
            // ---- grid barrier (leader-only fences) ----
            __syncthreads();
            if (tid == 0) {
                __threadfence();
                unsigned old = atomicAdd(bar_cnt, 1u);
                if (old == ENC_BLOCKS - 1) {
                    atomicExch(bar_cnt, 0u);
                    atomicAdd(bar_rel, 1u);
                }
                while (*(volatile unsigned*)bar_rel - relbase < (unsigned)t) {}
                __threadfence();
            }
            __syncthreads();

            float acc[4][3][4];
#pragma unroll
            for (int mt = 0; mt < 4; mt++)
#pragma unroll
                for (int nf = 0; nf < 3; nf++)
#pragma unroll
                    for (int q = 0; q < 4; q++) acc[mt][nf][q] = 0.f;

            const float* hb = enc_out + (size_t)(t - 1) * UU + w * 128;
            const float* r0p = hb + (size_t)lane * (SS * UU);
            const float* r1p = hb + (size_t)(lane + 32) * (SS * UU);

            float4 pf[8];
            E9_LOAD(0);
            for (int c = 0; c < 8; c++) {
                E9_STAGE();
                __syncwarp();
                if (c + 1 < 8) E9_LOAD(c + 1);
                E9_CONSUME(c);
                __syncwarp();
            }

            // write this warp's partial gh
#pragma unroll
            for (int mt = 0; mt < 4; mt++)
#pragma unroll
                for (int nf = 0; nf < 3; nf++) {
                    int r0 = mt * 16 + g;
                    float* dst = ghpW + r0 * GHP_ST + nf * 8 + qt * 2;
                    *reinterpret_cast<float2*>(dst) =
                        make_float2(acc[mt][nf][0], acc[mt][nf][1]);
                    *reinterpret_cast<float2*>(dst + 8 * GHP_ST) =
                        make_float2(acc[mt][nf][2], acc[mt][nf][3]);
                }
        }
        __syncthreads();

        // Epilogue: 2 (b,u) outputs per thread; reduce 8 ksplit partials
#pragma unroll
        for (int i = 0; i < 2; i++) {
            int b = (tid >> 3) + i * 32;
            float ghz = 0.f, ghr = 0.f, ghc = 0.f, hold = 0.f;
            if (t > 0) {
#pragma unroll
                for (int w2 = 0; w2 < EWARPS; w2++) {
                    const float* gg2 = ghp + w2 * (64 * GHP_ST) + b * GHP_ST;
                    ghz += gg2[edu];
                    ghr += gg2[8 + edu];
                    ghc += gg2[16 + edu];
                }
                hold = enc_out[(size_t)(b * SS + t - 1) * UU + eu];
            }
            const float* gxrow = gxe + (size_t)(b * SS + t) * G3;
            float z = sigmoidf_(gxrow[eu] + ghz + b1z);
            float r = sigmoidf_(gxrow[UU + eu] + ghr + b1r);
            float cc = tanhf(gxrow[2 * UU + eu] + r * (ghc + b1c));
            enc_out[(size_t)(b * SS + t) * UU + eu] = z * hold + (1.f - z) * cc;
        }
    }
}

// ---------------------------------------------------------------------------
// Persistent decoder: ONE launch, 64 blocks (one per batch), all 39 steps.
// ---------------------------------------------------------------------------
#define DEC_SMEM_FLOATS (SS * UU + G3 + UU + 64)
#define DEC_SMEM_BYTES (DEC_SMEM_FLOATS * 4)

__global__ __launch_bounds__(256, 1) void dec_persistent(
    const float* __restrict__ enc_out,
    const float* __restrict__ P,
    const float* __restrict__ gxd,
    const float* __restrict__ db1,
    float* __restrict__ hdec)
{
    extern __shared__ float dsm[];
    float* enc_sh = dsm;
    float* gxc    = dsm + SS * UU;
    float* h_sh   = gxc + G3;
    float* wsm    = h_sh + UU;

    const int b   = blockIdx.x;
    const int tid = threadIdx.x;
    const int warp = tid >> 5, lane = tid & 31;

    {
        const float4* src = reinterpret_cast<const float4*>(enc_out + (size_t)b * SS * UU);
        float4* dst = reinterpret_cast<float4*>(enc_sh);
        for (int i = tid; i < SS * UU / 4; i += 256) dst[i] = src[i];
    }
    __syncthreads();
    for (int i = tid; i < UU; i += 256) h_sh[i] = enc_sh[(SS - 1) * UU + i];
    __syncthreads();

    const float* Pb = P + (size_t)b * SS * G3;

    for (int t = 0; t < TD; t++) {
        {
            float acc[5] = {0.f, 0.f, 0.f, 0.f, 0.f};
#pragma unroll 4
            for (int i = 0; i < 32; i++) {
                int uidx = lane + 32 * i;
                float hv = h_sh[uidx];
#pragma unroll
                for (int q = 0; q < 5; q++)
                    acc[q] += hv * enc_sh[(warp * 5 + q) * UU + uidx];
            }
#pragma unroll
            for (int q = 0; q < 5; q++) {
                float v = acc[q];
                for (int o = 16; o; o >>= 1) v += __shfl_xor_sync(0xffffffffu, v, o);
                if (lane == 0) wsm[warp * 5 + q] = v;
            }
        }
        __syncthreads();

        if (tid == 0) {
            float mx = -1e30f;
            for (int s = 0; s < SS; s++) mx = fmaxf(mx, wsm[s]);
            float smv = 0.f;
            for (int s = 0; s < SS; s++) { float e = expf(wsm[s] - mx); wsm[s] = e; smv += e; }
            float inv = 1.f / smv;
            for (int s = 0; s < SS; s++) wsm[s] *= inv;
        }
        __syncthreads();

        {
            float a[12];
#pragma unroll
            for (int i = 0; i < 12; i++) a[i] = 0.f;
            for (int s = 0; s < SS; s++) {
                float w = wsm[s];
                const float* row = Pb + (size_t)s * G3;
#pragma unroll
                for (int i = 0; i < 12; i++)
                    a[i] += w * row[tid + i * 256];
            }
#pragma unroll
            for (int i = 0; i < 12; i++) gxc[tid + i * 256] = a[i];
        }
        __syncthreads();

        {
            const float* gx = gxd + (size_t)(b * TD + t) * G3;
            float* ho = hdec + (size_t)(b * TD + t) * UU;
#pragma unroll
            for (int i = 0; i < 4; i++) {
                int u = tid + i * 256;
                float z = sigmoidf_(gxc[u] + gx[u] + db1[u]);
                float r = sigmoidf_(gxc[UU + u] + gx[UU + u] + db1[UU + u]);
                float c = tanhf(gxc[2 * UU + u] + gx[2 * UU + u] + r * db1[2 * UU + u]);
                float hn = (1.f - z) * c;
                h_sh[u] = hn;
                ho[u] = hn;
            }
        }
        __syncthreads();
    }
}

// ---------------------------------------------------------------------------
extern "C" void kernel_launch(void* const* d_in, const int* in_sizes, int n_in,
                              void* d_out, int out_size)
{
    const int*   inp     = (const int*)d_in[0];
    const int*   targ    = (const int*)d_in[1];
    const float* enc_emb = (const float*)d_in[2];
    const float* enc_Wx  = (const float*)d_in[3];
    const float* enc_Wh  = (const float*)d_in[4];
    const float* enc_b   = (const float*)d_in[5];
    const float* dec_emb = (const float*)d_in[6];
    const float* dec_Wx  = (const float*)d_in[7];
    // d_in[8] = dec_Wh: provably unused (decoder GRU hidden input is zeros)
    const float* dec_b   = (const float*)d_in[9];
    const float* fc_W    = (const float*)d_in[10];
    const float* fc_b    = (const float*)d_in[11];
    float* out = (float*)d_out;

    float *gxe, *gxd, *enc_out, *P, *hdec;
    unsigned* bar;
    cudaGetSymbolAddress((void**)&gxe,     g_gxe);
    cudaGetSymbolAddress((void**)&gxd,     g_gxd);
    cudaGetSymbolAddress((void**)&enc_out, g_enc_out);
    cudaGetSymbolAddress((void**)&P,       g_P);
    cudaGetSymbolAddress((void**)&hdec,    g_hdec);
    cudaGetSymbolAddress((void**)&bar,     g_bar);

    cudaFuncSetAttribute(enc_persistent,
                         cudaFuncAttributeMaxDynamicSharedMemorySize, ENC_SMEM_BYTES);
    cudaFuncSetAttribute(dec_persistent,
                         cudaFuncAttributeMaxDynamicSharedMemorySize, DEC_SMEM_BYTES);

    // 1) Encoder gx: emb[inp] @ enc_Wx + b0  (tf32 tensor path; GRU gates are
    //    contractive so the per-step ~2e-4 gate-preactivation noise does not
    //    amplify through the recurrence — verified by bf16x3 encoder rounds)
    gemm_tf32<<<dim3(G3 / 128, (BB * SS + 127) / 128), 128>>>(
        nullptr, enc_emb, inp, SS, SS, EE,
        enc_Wx, G3, enc_b, gxe, BB * SS, G3, EE);

    // 2) Decoder xt-part gx (tf32 tensor path)
    gemm_tf32<<<dim3(G3 / 128, (BB * TD + 127) / 128), 128>>>(
        nullptr, dec_emb, targ, TD, SS, EE,
        dec_Wx + (size_t)UU * G3, G3, dec_b, gxd, BB * TD, G3, EE);

    // 3) Encoder recurrence: persistent bf16x3 tensor kernel (v6 structure)
    enc_persistent<<<ENC_BLOCKS, ENC_THREADS, ENC_SMEM_BYTES>>>(
        gxe, enc_Wh, enc_b + G3, enc_out, &bar[0], &bar[1]);

    // 4) P = enc_out @ dec_Wx[:U]   (tf32 tensor path)
    gemm_tf32<<<dim3(G3 / 128, (BB * SS + 127) / 128), 128>>>(
        enc_out, nullptr, nullptr, 1, 1, UU,
        dec_Wx, G3, nullptr, P, BB * SS, G3, UU);

    // 5) Decoder recurrence: ONE persistent kernel (batch-parallel)
    dec_persistent<<<BB, 256, DEC_SMEM_BYTES>>>(
        enc_out, P, gxd, dec_b + G3, hdec);

    // 6) Batched output projection (tf32 tensor path)
    gemm_tf32<<<dim3(VV / 128, (BB * TD + 127) / 128), 128>>>(
        hdec, nullptr, nullptr, 1, 1, UU,
        fc_W, VV, fc_b, out, BB * TD, VV, UU);
}